// round 16
// baseline (speedup 1.0000x reference)
#include <cuda_runtime.h>
#include <math.h>

#define NN   10000
#define EE   160000
#define GG   128
#define HID  25
#define DOUT 32
#define BEPS 1e-5f
#define NX   74          // node-tile blocks in k_y
#define TILE 136         // ceil(NN/NX), even

typedef unsigned long long u64;

// ---------------- f32x2 helpers (bit-exact packed fp32 FMA) ------------------
__device__ __forceinline__ u64 pk2(float a, float b) {
    u64 r; asm("mov.b64 %0, {%1, %2};" : "=l"(r) : "f"(a), "f"(b)); return r;
}
__device__ __forceinline__ u64 fma2(u64 a, u64 b, u64 c) {
    u64 d; asm("fma.rn.f32x2 %0, %1, %2, %3;" : "=l"(d) : "l"(a), "l"(b), "l"(c)); return d;
}
__device__ __forceinline__ void upk2(u64 u, float& a, float& b) {
    asm("mov.b64 {%0, %1}, %2;" : "=f"(a), "=f"(b) : "l"(u));
}

// ---------------- scratch ----------------------------------------------------
__device__ double d_mom[9];
__device__ float  d_wf[2][3][32];               // BN-folded first-linear weights
__device__ float  d_bf[2][32];
__device__ float  d_y[(size_t)NN * HID * DOUT]; // y[n][k][o]
__device__ float  d_xb[NN * DOUT];
__device__ float  d_x0[NN * DOUT];
__device__ int    d_degs[NN];                   // src out-degree
__device__ int    d_degd[NN];                   // dst in-degree
__device__ int    d_start[NN + 1];              // src CSR
__device__ int    d_cursor[NN];
__device__ int    d_start2[NN + 1];             // dst CSR
__device__ int    d_cursor2[NN];
__device__ int    d_qpos[EE];                   // src-sorted pos -> dst-sorted pos
__device__ float  d_eas[(size_t)EE * 3];        // edge attrs in src-sorted order
__device__ float  d_msgbuf[(size_t)EE * DOUT];  // messages at DST-sorted positions
__device__ float  d_gsum[GG * DOUT];
__device__ float  d_gcnt[GG];

// ---------------- default stream: CSR prologue -------------------------------
__global__ void k_deg_both(const int* __restrict__ ei) {
    int i = (blockIdx.x * blockDim.x + threadIdx.x) * 4;
    if (i < EE) {
        int4 s = *(const int4*)(ei + i);
        int4 t = *(const int4*)(ei + EE + i);
        atomicAdd(&d_degs[s.x], 1);
        atomicAdd(&d_degs[s.y], 1);
        atomicAdd(&d_degs[s.z], 1);
        atomicAdd(&d_degs[s.w], 1);
        atomicAdd(&d_degd[t.x], 1);
        atomicAdd(&d_degd[t.y], 1);
        atomicAdd(&d_degd[t.z], 1);
        atomicAdd(&d_degd[t.w], 1);
    }
}

// grid=2: block 0 scans src degrees, block 1 scans dst degrees
__global__ void k_scan2() {
    __shared__ int s[1024];
    const int t = threadIdx.x;
    const int* din = blockIdx.x ? d_degd : d_degs;
    int* dsts = blockIdx.x ? d_start2 : d_start;
    int* dstc = blockIdx.x ? d_cursor2 : d_cursor;
    const int CH = (NN + 1023) / 1024;
    int loc[CH];
    int base = t * CH;
    int run = 0;
#pragma unroll
    for (int i = 0; i < CH; i++) {
        int v = (base + i < NN) ? din[base + i] : 0;
        loc[i] = run; run += v;
    }
    s[t] = run;
    __syncthreads();
    for (int off = 1; off < 1024; off <<= 1) {
        int v = (t >= off) ? s[t - off] : 0;
        __syncthreads();
        s[t] += v;
        __syncthreads();
    }
    int excl = (t > 0) ? s[t - 1] : 0;
#pragma unroll
    for (int i = 0; i < CH; i++)
        if (base + i < NN) {
            int v = excl + loc[i];
            dsts[base + i] = v;
            dstc[base + i] = v;
        }
    if (t == 1023) dsts[NN] = s[1023];
}

// src-sorted attrs + src-pos -> dst-pos map
__global__ void k_scatter(const int* __restrict__ ei, const float* __restrict__ ea) {
    int i = (blockIdx.x * blockDim.x + threadIdx.x) * 4;
    if (i < EE) {
        int4 s = *(const int4*)(ei + i);
        int4 t = *(const int4*)(ei + EE + i);
        int p0 = atomicAdd(&d_cursor[s.x], 1);
        int p1 = atomicAdd(&d_cursor[s.y], 1);
        int p2 = atomicAdd(&d_cursor[s.z], 1);
        int p3 = atomicAdd(&d_cursor[s.w], 1);
        int pp[4] = {p0, p1, p2, p3};
#pragma unroll
        for (int j = 0; j < 4; j++) {
            int e = i + j, p = pp[j];
            d_eas[3 * (size_t)p]     = ea[3 * e];
            d_eas[3 * (size_t)p + 1] = ea[3 * e + 1];
            d_eas[3 * (size_t)p + 2] = ea[3 * e + 2];
        }
        int q0 = atomicAdd(&d_cursor2[t.x], 1);
        int q1 = atomicAdd(&d_cursor2[t.y], 1);
        int q2 = atomicAdd(&d_cursor2[t.z], 1);
        int q3 = atomicAdd(&d_cursor2[t.w], 1);
        d_qpos[p0] = q0;
        d_qpos[p1] = q1;
        d_qpos[p2] = q2;
        d_qpos[p3] = q3;
    }
}

// ---------------- stream s1: edge-attr moments + BN fold ---------------------
__global__ void k_mom(const float* __restrict__ ea) {
    __shared__ float smom[9 * 8];
    const int tid = threadIdx.x;
    const int t = blockIdx.x * 256 + tid;
    float m[9] = {0.f, 0.f, 0.f, 0.f, 0.f, 0.f, 0.f, 0.f, 0.f};
    int base = t * 12;
    if (base < EE * 3) {
        const float4* p = (const float4*)(ea + base);
        float4 A = p[0], B = p[1], C = p[2];
        float ax[4] = {A.x, A.w, B.z, C.y};
        float ay[4] = {A.y, B.x, B.w, C.z};
        float az[4] = {A.z, B.y, C.x, C.w};
#pragma unroll
        for (int j = 0; j < 4; j++) {
            float a0 = ax[j], a1 = ay[j], a2 = az[j];
            m[0] += a0; m[1] += a1; m[2] += a2;
            m[3] = fmaf(a0, a0, m[3]); m[4] = fmaf(a0, a1, m[4]);
            m[5] = fmaf(a0, a2, m[5]); m[6] = fmaf(a1, a1, m[6]);
            m[7] = fmaf(a1, a2, m[7]); m[8] = fmaf(a2, a2, m[8]);
        }
    }
    int lane = tid & 31, w = tid >> 5;
#pragma unroll
    for (int j = 0; j < 9; j++) {
        float v = m[j];
#pragma unroll
        for (int off = 16; off; off >>= 1) v += __shfl_down_sync(0xffffffffu, v, off);
        if (lane == 0) smom[j * 8 + w] = v;
    }
    __syncthreads();
    if (tid < 9) {
        float s = 0.f;
#pragma unroll
        for (int j = 0; j < 8; j++) s += smom[tid * 8 + j];
        atomicAdd(&d_mom[tid], (double)s);
    }
}

__global__ void k_bn_both(const float* __restrict__ g0, const float* __restrict__ be0,
                          const float* __restrict__ g1, const float* __restrict__ be1,
                          const float* __restrict__ w1a, const float* __restrict__ b1a,
                          const float* __restrict__ w1b, const float* __restrict__ b1b) {
    int t = threadIdx.x;
    int layer = t >> 5, k = t & 31;
    if (layer < 2 && k < HID) {
        const float* w1 = layer ? w1b : w1a;
        const float* b1 = layer ? b1b : b1a;
        const float* g  = layer ? g1  : g0;
        const float* be = layer ? be1 : be0;
        double wa = w1[k], wb = w1[HID + k], wc = w1[2 * HID + k], b = b1[k];
        double S0 = d_mom[0], S1 = d_mom[1], S2 = d_mom[2];
        double M00 = d_mom[3], M01 = d_mom[4], M02 = d_mom[5];
        double M11 = d_mom[6], M12 = d_mom[7], M22 = d_mom[8];
        double lin = S0 * wa + S1 * wb + S2 * wc;
        double mu  = (lin + (double)EE * b) / (double)EE;
        double sq  = wa * wa * M00 + M11 * wb * wb + M22 * wc * wc
                   + 2.0 * (wa * wb * M01 + wa * wc * M02 + wb * wc * M12)
                   + 2.0 * b * lin + (double)EE * b * b;
        double var = sq / (double)EE - mu * mu;
        float rs = rsqrtf((float)var + BEPS);
        float sc = rs * g[k];
        float sh = be[k] - (float)mu * sc;
        d_wf[layer][0][k] = (float)wa * sc;
        d_wf[layer][1][k] = (float)wb * sc;
        d_wf[layer][2][k] = (float)wc * sc;
        d_bf[layer][k]    = (float)b * sc + sh;
    }
}

// ---------------- stream s2: graph counts ------------------------------------
__global__ void k_gcnt(const int* __restrict__ batch) {
    int n = blockIdx.x * blockDim.x + threadIdx.x;
    if (n < NN) atomicAdd(&d_gcnt[batch[n]], 1.f);
}

// ---------------- per-node y[n,k,o] + xb -------------------------------------
template <int DIN>
__global__ void k_y(const float* __restrict__ xin_ext, int use_ext,
                    const float* __restrict__ w2, const float* __restrict__ b2) {
    __shared__ __align__(16) float xs[DIN][TILE];
    const float* xin = use_ext ? xin_ext : d_x0;
    const int tid = threadIdx.x, lane = tid & 31, w = tid >> 5;
    const int k = blockIdx.y;
    const int nbeg = blockIdx.x * TILE;

    for (int idx = tid; idx < TILE * DIN; idx += 128) {
        int t = idx / DIN, i = idx % DIN;
        int n = nbeg + t;
        xs[i][t] = (n < NN) ? xin[(size_t)n * DIN + i] : 0.f;
    }
    __syncthreads();

    float wreg[DIN];
    if (k < HID) {
#pragma unroll
        for (int i = 0; i < DIN; i++)
            wreg[i] = __ldg(&w2[(k * DIN + i) * DOUT + lane]);
        for (int p = w; p < TILE / 2; p += 4) {
            u64 acc = 0;
#pragma unroll
            for (int i = 0; i < DIN; i++) {
                u64 xv = *(const u64*)&xs[i][2 * p];
                acc = fma2(xv, pk2(wreg[i], wreg[i]), acc);
            }
            float va, vb; upk2(acc, va, vb);
            int n = nbeg + 2 * p;
            if (n < NN)     d_y[((size_t)n * HID + k) * DOUT + lane] = va;
            if (n + 1 < NN) d_y[((size_t)(n + 1) * HID + k) * DOUT + lane] = vb;
        }
    } else {
#pragma unroll
        for (int i = 0; i < DIN; i++)
            wreg[i] = __ldg(&b2[i * DOUT + lane]);
        for (int p = w; p < TILE / 2; p += 4) {
            u64 acc = 0;
#pragma unroll
            for (int i = 0; i < DIN; i++) {
                u64 xv = *(const u64*)&xs[i][2 * p];
                acc = fma2(xv, pk2(wreg[i], wreg[i]), acc);
            }
            float va, vb; upk2(acc, va, vb);
            int n = nbeg + 2 * p;
            if (n < NN)     d_xb[n * DOUT + lane] = va;
            if (n + 1 < NN) d_xb[(n + 1) * DOUT + lane] = vb;
        }
    }
}

// ---------------- messages: warp/src, inline h, direct dst-slot store --------
__global__ void k_msg(int layer) {
    __shared__ __align__(16) float sw[8][2][32];
    __shared__ float swf0[32], swf1[32], swf2[32], sbf[32];
    const int wip  = threadIdx.x >> 5;
    const int gw   = (blockIdx.x * blockDim.x + threadIdx.x) >> 5;
    const int lane = threadIdx.x & 31;
    if (threadIdx.x < 32) {
        swf0[threadIdx.x] = d_wf[layer][0][threadIdx.x];
        swf1[threadIdx.x] = d_wf[layer][1][threadIdx.x];
        swf2[threadIdx.x] = d_wf[layer][2][threadIdx.x];
        sbf[threadIdx.x]  = d_bf[layer][threadIdx.x];
    }
    __syncthreads();
    if (gw >= NN) return;
    int beg = d_start[gw], end = d_start[gw + 1];
    if (beg == end) return;

    const float wf0 = swf0[lane], wf1 = swf1[lane], wf2 = swf2[lane], bf = sbf[lane];
    float xb = d_xb[gw * DOUT + lane];
    const float* yrow = d_y + (size_t)gw * HID * DOUT;
    u64 yp[12]; float y24;
#pragma unroll
    for (int k = 0; k < 12; k++)
        yp[k] = pk2(yrow[(2 * k) * DOUT + lane], yrow[(2 * k + 1) * DOUT + lane]);
    y24 = yrow[24 * DOUT + lane];

    // prefetch: sorted attrs + dst-slot stream sequentially over the warp's range
    float a0n = d_eas[3 * (size_t)beg];
    float a1n = d_eas[3 * (size_t)beg + 1];
    float a2n = d_eas[3 * (size_t)beg + 2];
    int   qn  = d_qpos[beg];

    for (int p = beg; p < end; p++) {
        float hv = fmaxf(fmaf(a0n, wf0, fmaf(a1n, wf1, fmaf(a2n, wf2, bf))), 0.f);
        int buf = p & 1;
        sw[wip][buf][lane] = hv;
        int q = qn;
        if (p + 1 < end) {
            a0n = d_eas[3 * (size_t)(p + 1)];
            a1n = d_eas[3 * (size_t)(p + 1) + 1];
            a2n = d_eas[3 * (size_t)(p + 1) + 2];
            qn  = d_qpos[p + 1];
        }
        __syncwarp();
        const u64* hp = (const u64*)sw[wip][buf];
        u64 acc = 0;
#pragma unroll
        for (int k = 0; k < 12; k++) acc = fma2(hp[k], yp[k], acc);
        float ma, mb; upk2(acc, ma, mb);
        float m = fmaf(sw[wip][buf][24], y24, xb + ma + mb);
        d_msgbuf[(size_t)q * DOUT + lane] = m;      // one random 128B line/edge, fire-and-forget
    }
}

// ---------------- aggregate: warp/dst, SEQUENTIAL stream + root + ELU (+pool) -
template <int DIN>
__global__ void k_agg(const float* __restrict__ xin_ext, int use_ext,
                      const float* __restrict__ wr, const float* __restrict__ bc,
                      const int* __restrict__ batch, int last) {
    const int gw   = (blockIdx.x * blockDim.x + threadIdx.x) >> 5;
    const int lane = threadIdx.x & 31;
    if (gw >= NN) return;
    int beg = d_start2[gw], end = d_start2[gw + 1];

    float s0 = 0.f, s1 = 0.f, s2 = 0.f, s3 = 0.f;
    const float* mb = d_msgbuf + (size_t)beg * DOUT + lane;
    int cnt = end - beg;
    int q = 0;
    for (; q + 4 <= cnt; q += 4) {              // sequential, coalesced, MLP-4
        s0 += mb[(size_t)q * DOUT];
        s1 += mb[(size_t)(q + 1) * DOUT];
        s2 += mb[(size_t)(q + 2) * DOUT];
        s3 += mb[(size_t)(q + 3) * DOUT];
    }
    for (; q < cnt; q++) s0 += mb[(size_t)q * DOUT];
    float acc = (s0 + s1) + (s2 + s3);

    float dg = fmaxf((float)cnt, 1.f);
    const float* xin = use_ext ? xin_ext : d_x0;
    float xi = (lane < DIN) ? xin[(size_t)gw * DIN + lane] : 0.f;
    float root = __ldg(&bc[lane]);
#pragma unroll
    for (int i = 0; i < DIN; i++)
        root = fmaf(__shfl_sync(0xffffffffu, xi, i), __ldg(&wr[i * DOUT + lane]), root);
    float v = acc / dg + root;
    v = (v > 0.f) ? v : expm1f(v);
    if (last) atomicAdd(&d_gsum[batch[gw] * DOUT + lane], v);
    else      d_x0[gw * DOUT + lane] = v;
}

// ---------------- final fc ---------------------------------------------------
__global__ void kp_out(const float* __restrict__ wfc, const float* __restrict__ bfc,
                       float* __restrict__ out) {
    int g = threadIdx.x;
    if (g < GG) {
        float c = fmaxf(d_gcnt[g], 1.f);
        float acc = 0.f;
#pragma unroll
        for (int o = 0; o < DOUT; o++)
            acc = fmaf(d_gsum[g * DOUT + o] / c, __ldg(&wfc[o]), acc);
        out[g] = acc + bfc[0];
    }
}

// ---------------- launch -----------------------------------------------------
extern "C" void kernel_launch(void* const* d_in, const int* in_sizes, int n_in,
                              void* d_out, int out_size) {
    (void)in_sizes; (void)n_in; (void)out_size;
    const float* x     = (const float*)d_in[0];
    const float* ea    = (const float*)d_in[1];
    const int*   ei    = (const int*)d_in[2];
    const int*   batch = (const int*)d_in[3];
    const float* w1_0 = (const float*)d_in[4];
    const float* b1_0 = (const float*)d_in[5];
    const float* g_0  = (const float*)d_in[6];
    const float* be_0 = (const float*)d_in[7];
    const float* w2_0 = (const float*)d_in[8];
    const float* b2_0 = (const float*)d_in[9];
    const float* wr_0 = (const float*)d_in[10];
    const float* bc_0 = (const float*)d_in[11];
    const float* w1_1 = (const float*)d_in[12];
    const float* b1_1 = (const float*)d_in[13];
    const float* g_1  = (const float*)d_in[14];
    const float* be_1 = (const float*)d_in[15];
    const float* w2_1 = (const float*)d_in[16];
    const float* b2_1 = (const float*)d_in[17];
    const float* wr_1 = (const float*)d_in[18];
    const float* bc_1 = (const float*)d_in[19];
    const float* wfc  = (const float*)d_in[20];
    const float* bfc  = (const float*)d_in[21];
    float* out = (float*)d_out;

    static cudaStream_t s1 = nullptr, s2 = nullptr;
    static cudaEvent_t ev0, ev1, ev2;
    static void *p_degs, *p_degd, *p_gsum, *p_gcnt, *p_mom;
    if (!s1) {
        cudaStreamCreateWithFlags(&s1, cudaStreamNonBlocking);
        cudaStreamCreateWithFlags(&s2, cudaStreamNonBlocking);
        cudaEventCreateWithFlags(&ev0, cudaEventDisableTiming);
        cudaEventCreateWithFlags(&ev1, cudaEventDisableTiming);
        cudaEventCreateWithFlags(&ev2, cudaEventDisableTiming);
        cudaGetSymbolAddress(&p_degs, d_degs);
        cudaGetSymbolAddress(&p_degd, d_degd);
        cudaGetSymbolAddress(&p_gsum, d_gsum);
        cudaGetSymbolAddress(&p_gcnt, d_gcnt);
        cudaGetSymbolAddress(&p_mom,  d_mom);
    }

    // fork
    cudaEventRecord(ev0, 0);
    cudaStreamWaitEvent(s1, ev0, 0);
    cudaStreamWaitEvent(s2, ev0, 0);

    // default: dual CSR prologue (critical path)
    cudaMemsetAsync(p_degs, 0, NN * sizeof(int), 0);
    cudaMemsetAsync(p_degd, 0, NN * sizeof(int), 0);
    k_deg_both<<<(EE / 4 + 255) / 256, 256>>>(ei);
    k_scan2<<<2, 1024>>>();
    k_scatter<<<(EE / 4 + 255) / 256, 256>>>(ei, ea);

    // s1: moments -> BN fold
    cudaMemsetAsync(p_mom, 0, 9 * sizeof(double), s1);
    k_mom<<<(EE / 4 + 255) / 256, 256, 0, s1>>>(ea);
    k_bn_both<<<1, 64, 0, s1>>>(g_0, be_0, g_1, be_1, w1_0, b1_0, w1_1, b1_1);
    cudaEventRecord(ev1, s1);

    // s2: pool counts + layer-0 y precompute
    cudaMemsetAsync(p_gsum, 0, GG * DOUT * sizeof(float), s2);
    cudaMemsetAsync(p_gcnt, 0, GG * sizeof(float), s2);
    k_gcnt<<<(NN + 255) / 256, 256, 0, s2>>>(batch);
    k_y<16><<<dim3(NX, HID + 1), 128, 0, s2>>>(x, 1, w2_0, b2_0);
    cudaEventRecord(ev2, s2);

    // join
    cudaStreamWaitEvent(0, ev1, 0);
    cudaStreamWaitEvent(0, ev2, 0);

    // layer 0
    k_msg<<<(NN * 32 + 255) / 256, 256>>>(0);
    k_agg<16><<<(NN * 32 + 255) / 256, 256>>>(x, 1, wr_0, bc_0, batch, 0);

    // layer 1
    k_y<32><<<dim3(NX, HID + 1), 128>>>(nullptr, 0, w2_1, b2_1);
    k_msg<<<(NN * 32 + 255) / 256, 256>>>(1);
    k_agg<32><<<(NN * 32 + 255) / 256, 256>>>(nullptr, 0, wr_1, bc_1, batch, 1);

    // fc
    kp_out<<<1, 128>>>(wfc, bfc, out);
}

// round 17
// speedup vs baseline: 1.7229x; 1.7229x over previous
#include <cuda_runtime.h>
#include <math.h>

#define NN   10000
#define EE   160000
#define GG   128
#define HID  25
#define DOUT 32
#define BEPS 1e-5f
#define NX   74          // node-tile blocks in k_y
#define TILE 136         // ceil(NN/NX), even

typedef unsigned long long u64;

// ---------------- f32x2 helpers (bit-exact packed fp32 FMA) ------------------
__device__ __forceinline__ u64 pk2(float a, float b) {
    u64 r; asm("mov.b64 %0, {%1, %2};" : "=l"(r) : "f"(a), "f"(b)); return r;
}
__device__ __forceinline__ u64 fma2(u64 a, u64 b, u64 c) {
    u64 d; asm("fma.rn.f32x2 %0, %1, %2, %3;" : "=l"(d) : "l"(a), "l"(b), "l"(c)); return d;
}
__device__ __forceinline__ void upk2(u64 u, float& a, float& b) {
    asm("mov.b64 {%0, %1}, %2;" : "=f"(a), "=f"(b) : "l"(u));
}

// ---------------- scratch ----------------------------------------------------
__device__ double d_mom[9];
__device__ float  d_wf[2][3][32];               // BN-folded first-linear weights
__device__ float  d_bf[2][32];
__device__ float  d_y[(size_t)NN * HID * DOUT]; // y[n][k][o]
__device__ float  d_xb[NN * DOUT];
__device__ float  d_agg[NN * DOUT];
__device__ float  d_x0[NN * DOUT];
__device__ float  d_deg[NN];                    // dst in-degree
__device__ int    d_degs[NN];                   // src out-degree
__device__ int    d_start[NN + 1];
__device__ int    d_cursor[NN];
__device__ float  d_eas[(size_t)EE * 3];        // edge attrs in src-sorted order
__device__ int    d_dsts[EE];
__device__ float  d_gsum[GG * DOUT];
__device__ float  d_gcnt[GG];

// ---------------- default stream: CSR prologue -------------------------------
// 4 edges per thread, int4 loads (EE % 4 == 0)
__global__ void k_deg_src(const int* __restrict__ ei) {
    int i = (blockIdx.x * blockDim.x + threadIdx.x) * 4;
    if (i < EE) {
        int4 s = *(const int4*)(ei + i);
        atomicAdd(&d_degs[s.x], 1);
        atomicAdd(&d_degs[s.y], 1);
        atomicAdd(&d_degs[s.z], 1);
        atomicAdd(&d_degs[s.w], 1);
    }
}

__global__ void k_scan() {
    __shared__ int s[1024];
    const int t = threadIdx.x;
    const int CH = (NN + 1023) / 1024;
    int loc[CH];
    int base = t * CH;
    int run = 0;
#pragma unroll
    for (int i = 0; i < CH; i++) {
        int v = (base + i < NN) ? d_degs[base + i] : 0;
        loc[i] = run; run += v;
    }
    s[t] = run;
    __syncthreads();
    for (int off = 1; off < 1024; off <<= 1) {
        int v = (t >= off) ? s[t - off] : 0;
        __syncthreads();
        s[t] += v;
        __syncthreads();
    }
    int excl = (t > 0) ? s[t - 1] : 0;
#pragma unroll
    for (int i = 0; i < CH; i++)
        if (base + i < NN) {
            int v = excl + loc[i];
            d_start[base + i]  = v;
            d_cursor[base + i] = v;
        }
    if (t == 1023) d_start[NN] = s[1023];
}

// sorted edge attrs + dst per sorted pos (no d_perm needed anymore)
__global__ void k_scatter(const int* __restrict__ ei, const float* __restrict__ ea) {
    int i = (blockIdx.x * blockDim.x + threadIdx.x) * 4;
    if (i < EE) {
        int4 s = *(const int4*)(ei + i);
        int4 t = *(const int4*)(ei + EE + i);
        int p0 = atomicAdd(&d_cursor[s.x], 1);
        int p1 = atomicAdd(&d_cursor[s.y], 1);
        int p2 = atomicAdd(&d_cursor[s.z], 1);
        int p3 = atomicAdd(&d_cursor[s.w], 1);
        d_dsts[p0] = t.x;
        d_dsts[p1] = t.y;
        d_dsts[p2] = t.z;
        d_dsts[p3] = t.w;
        int pp[4] = {p0, p1, p2, p3};
#pragma unroll
        for (int j = 0; j < 4; j++) {
            int e = i + j, p = pp[j];
            d_eas[3 * (size_t)p]     = ea[3 * e];
            d_eas[3 * (size_t)p + 1] = ea[3 * e + 1];
            d_eas[3 * (size_t)p + 2] = ea[3 * e + 2];
        }
    }
}

// ---------------- stream s2: dst degree + graph counts -----------------------
__global__ void k_deg_dst(const int* __restrict__ ei, const int* __restrict__ batch) {
    int tid = blockIdx.x * blockDim.x + threadIdx.x;
    int i = tid * 4;
    if (i < EE) {
        int4 t = *(const int4*)(ei + EE + i);
        atomicAdd(&d_deg[t.x], 1.f);
        atomicAdd(&d_deg[t.y], 1.f);
        atomicAdd(&d_deg[t.z], 1.f);
        atomicAdd(&d_deg[t.w], 1.f);
    }
    if (tid < NN) atomicAdd(&d_gcnt[batch[tid]], 1.f);
}

// ---------------- stream s1: edge-attr moments (4 edges/thread) --------------
__global__ void k_mom(const float* __restrict__ ea) {
    __shared__ float smom[9 * 8];
    const int tid = threadIdx.x;
    const int t = blockIdx.x * 256 + tid;
    float m[9] = {0.f, 0.f, 0.f, 0.f, 0.f, 0.f, 0.f, 0.f, 0.f};
    int base = t * 12;
    if (base < EE * 3) {
        const float4* p = (const float4*)(ea + base);
        float4 A = p[0], B = p[1], C = p[2];
        float ax[4] = {A.x, A.w, B.z, C.y};
        float ay[4] = {A.y, B.x, B.w, C.z};
        float az[4] = {A.z, B.y, C.x, C.w};
#pragma unroll
        for (int j = 0; j < 4; j++) {
            float a0 = ax[j], a1 = ay[j], a2 = az[j];
            m[0] += a0; m[1] += a1; m[2] += a2;
            m[3] = fmaf(a0, a0, m[3]); m[4] = fmaf(a0, a1, m[4]);
            m[5] = fmaf(a0, a2, m[5]); m[6] = fmaf(a1, a1, m[6]);
            m[7] = fmaf(a1, a2, m[7]); m[8] = fmaf(a2, a2, m[8]);
        }
    }
    int lane = tid & 31, w = tid >> 5;
#pragma unroll
    for (int j = 0; j < 9; j++) {
        float v = m[j];
#pragma unroll
        for (int off = 16; off; off >>= 1) v += __shfl_down_sync(0xffffffffu, v, off);
        if (lane == 0) smom[j * 8 + w] = v;
    }
    __syncthreads();
    if (tid < 9) {
        float s = 0.f;
#pragma unroll
        for (int j = 0; j < 8; j++) s += smom[tid * 8 + j];
        atomicAdd(&d_mom[tid], (double)s);
    }
}

// BN fold from moments -> folded first-linear weights (both layers)
__global__ void k_bn_both(const float* __restrict__ g0, const float* __restrict__ be0,
                          const float* __restrict__ g1, const float* __restrict__ be1,
                          const float* __restrict__ w1a, const float* __restrict__ b1a,
                          const float* __restrict__ w1b, const float* __restrict__ b1b) {
    int t = threadIdx.x;
    int layer = t >> 5, k = t & 31;
    if (layer < 2 && k < HID) {
        const float* w1 = layer ? w1b : w1a;
        const float* b1 = layer ? b1b : b1a;
        const float* g  = layer ? g1  : g0;
        const float* be = layer ? be1 : be0;
        double wa = w1[k], wb = w1[HID + k], wc = w1[2 * HID + k], b = b1[k];
        double S0 = d_mom[0], S1 = d_mom[1], S2 = d_mom[2];
        double M00 = d_mom[3], M01 = d_mom[4], M02 = d_mom[5];
        double M11 = d_mom[6], M12 = d_mom[7], M22 = d_mom[8];
        double lin = S0 * wa + S1 * wb + S2 * wc;
        double mu  = (lin + (double)EE * b) / (double)EE;
        double sq  = wa * wa * M00 + M11 * wb * wb + M22 * wc * wc
                   + 2.0 * (wa * wb * M01 + wa * wc * M02 + wb * wc * M12)
                   + 2.0 * b * lin + (double)EE * b * b;
        double var = sq / (double)EE - mu * mu;
        float rs = rsqrtf((float)var + BEPS);
        float sc = rs * g[k];
        float sh = be[k] - (float)mu * sc;
        d_wf[layer][0][k] = (float)wa * sc;
        d_wf[layer][1][k] = (float)wb * sc;
        d_wf[layer][2][k] = (float)wc * sc;
        d_bf[layer][k]    = (float)b * sc + sh;
    }
}

// ---------------- per-node y[n,k,o] + xb, zero agg ---------------------------
template <int DIN>
__global__ void k_y(const float* __restrict__ xin_ext, int use_ext,
                    const float* __restrict__ w2, const float* __restrict__ b2) {
    __shared__ __align__(16) float xs[DIN][TILE];
    const float* xin = use_ext ? xin_ext : d_x0;
    const int tid = threadIdx.x, lane = tid & 31, w = tid >> 5;
    const int k = blockIdx.y;
    const int nbeg = blockIdx.x * TILE;

    for (int idx = tid; idx < TILE * DIN; idx += 128) {
        int t = idx / DIN, i = idx % DIN;
        int n = nbeg + t;
        xs[i][t] = (n < NN) ? xin[(size_t)n * DIN + i] : 0.f;
    }
    __syncthreads();

    float wreg[DIN];
    if (k < HID) {
#pragma unroll
        for (int i = 0; i < DIN; i++)
            wreg[i] = __ldg(&w2[(k * DIN + i) * DOUT + lane]);
        for (int p = w; p < TILE / 2; p += 4) {
            u64 acc = 0;
#pragma unroll
            for (int i = 0; i < DIN; i++) {
                u64 xv = *(const u64*)&xs[i][2 * p];
                acc = fma2(xv, pk2(wreg[i], wreg[i]), acc);
            }
            float va, vb; upk2(acc, va, vb);
            int n = nbeg + 2 * p;
            if (n < NN)     d_y[((size_t)n * HID + k) * DOUT + lane] = va;
            if (n + 1 < NN) d_y[((size_t)(n + 1) * HID + k) * DOUT + lane] = vb;
        }
    } else {
#pragma unroll
        for (int i = 0; i < DIN; i++)
            wreg[i] = __ldg(&b2[i * DOUT + lane]);
        for (int p = w; p < TILE / 2; p += 4) {
            u64 acc = 0;
#pragma unroll
            for (int i = 0; i < DIN; i++) {
                u64 xv = *(const u64*)&xs[i][2 * p];
                acc = fma2(xv, pk2(wreg[i], wreg[i]), acc);
            }
            float va, vb; upk2(acc, va, vb);
            int n = nbeg + 2 * p;
            if (n < NN)     { d_xb[n * DOUT + lane] = va;
                              d_agg[n * DOUT + lane] = 0.f; }
            if (n + 1 < NN) { d_xb[(n + 1) * DOUT + lane] = vb;
                              d_agg[(n + 1) * DOUT + lane] = 0.f; }
        }
    }
}

// ---------------- messages: warp/src, inline h from STREAMING attrs ----------
__global__ void k_msg(int layer) {
    __shared__ __align__(16) float sw[8][2][32];
    __shared__ float swf0[32], swf1[32], swf2[32], sbf[32];
    const int wip  = threadIdx.x >> 5;
    const int gw   = (blockIdx.x * blockDim.x + threadIdx.x) >> 5;
    const int lane = threadIdx.x & 31;
    if (threadIdx.x < 32) {
        swf0[threadIdx.x] = d_wf[layer][0][threadIdx.x];
        swf1[threadIdx.x] = d_wf[layer][1][threadIdx.x];
        swf2[threadIdx.x] = d_wf[layer][2][threadIdx.x];
        sbf[threadIdx.x]  = d_bf[layer][threadIdx.x];
    }
    __syncthreads();
    if (gw >= NN) return;
    int beg = d_start[gw], end = d_start[gw + 1];
    if (beg == end) return;

    const float wf0 = swf0[lane], wf1 = swf1[lane], wf2 = swf2[lane], bf = sbf[lane];
    float xb = d_xb[gw * DOUT + lane];
    const float* yrow = d_y + (size_t)gw * HID * DOUT;
    u64 yp[12]; float y24;
#pragma unroll
    for (int k = 0; k < 12; k++)
        yp[k] = pk2(yrow[(2 * k) * DOUT + lane], yrow[(2 * k + 1) * DOUT + lane]);
    y24 = yrow[24 * DOUT + lane];

    // prefetch: attrs stream sequentially over this warp's sorted range
    float a0n = d_eas[3 * (size_t)beg];
    float a1n = d_eas[3 * (size_t)beg + 1];
    float a2n = d_eas[3 * (size_t)beg + 2];
    int   dst_next = d_dsts[beg];

    for (int p = beg; p < end; p++) {
        float hv = fmaxf(fmaf(a0n, wf0, fmaf(a1n, wf1, fmaf(a2n, wf2, bf))), 0.f);
        int buf = p & 1;
        sw[wip][buf][lane] = hv;
        int dst = dst_next;
        if (p + 1 < end) {
            a0n = d_eas[3 * (size_t)(p + 1)];
            a1n = d_eas[3 * (size_t)(p + 1) + 1];
            a2n = d_eas[3 * (size_t)(p + 1) + 2];
            dst_next = d_dsts[p + 1];
        }
        __syncwarp();
        const u64* hp = (const u64*)sw[wip][buf];
        u64 acc = 0;
#pragma unroll
        for (int k = 0; k < 12; k++) acc = fma2(hp[k], yp[k], acc);
        float ma, mb; upk2(acc, ma, mb);
        float m = fmaf(sw[wip][buf][24], y24, xb + ma + mb);
        atomicAdd(&d_agg[dst * DOUT + lane], m);
    }
}

// ---------------- node update (+ pooling on last layer) ----------------------
template <int DIN>
__global__ void k_x(const float* __restrict__ xin_ext, int use_ext,
                    const float* __restrict__ wr, const float* __restrict__ bc,
                    const int* __restrict__ batch, int last) {
    int idx = blockIdx.x * blockDim.x + threadIdx.x;
    if (idx >= NN * DOUT) return;
    int n = idx / DOUT, o = idx % DOUT;
    const float* xin = use_ext ? xin_ext : d_x0;
    float root = __ldg(&bc[o]);
#pragma unroll
    for (int i = 0; i < DIN; i++)
        root = fmaf(xin[(size_t)n * DIN + i], __ldg(&wr[i * DOUT + o]), root);
    float dg = fmaxf(d_deg[n], 1.f);
    float v = d_agg[idx] / dg + root;
    v = (v > 0.f) ? v : expm1f(v);
    if (last) atomicAdd(&d_gsum[batch[n] * DOUT + o], v);
    else      d_x0[idx] = v;
}

// ---------------- final fc ---------------------------------------------------
__global__ void kp_out(const float* __restrict__ wfc, const float* __restrict__ bfc,
                       float* __restrict__ out) {
    int g = threadIdx.x;
    if (g < GG) {
        float c = fmaxf(d_gcnt[g], 1.f);
        float acc = 0.f;
#pragma unroll
        for (int o = 0; o < DOUT; o++)
            acc = fmaf(d_gsum[g * DOUT + o] / c, __ldg(&wfc[o]), acc);
        out[g] = acc + bfc[0];
    }
}

// ---------------- launch -----------------------------------------------------
extern "C" void kernel_launch(void* const* d_in, const int* in_sizes, int n_in,
                              void* d_out, int out_size) {
    (void)in_sizes; (void)n_in; (void)out_size;
    const float* x     = (const float*)d_in[0];
    const float* ea    = (const float*)d_in[1];
    const int*   ei    = (const int*)d_in[2];
    const int*   batch = (const int*)d_in[3];
    const float* w1_0 = (const float*)d_in[4];
    const float* b1_0 = (const float*)d_in[5];
    const float* g_0  = (const float*)d_in[6];
    const float* be_0 = (const float*)d_in[7];
    const float* w2_0 = (const float*)d_in[8];
    const float* b2_0 = (const float*)d_in[9];
    const float* wr_0 = (const float*)d_in[10];
    const float* bc_0 = (const float*)d_in[11];
    const float* w1_1 = (const float*)d_in[12];
    const float* b1_1 = (const float*)d_in[13];
    const float* g_1  = (const float*)d_in[14];
    const float* be_1 = (const float*)d_in[15];
    const float* w2_1 = (const float*)d_in[16];
    const float* b2_1 = (const float*)d_in[17];
    const float* wr_1 = (const float*)d_in[18];
    const float* bc_1 = (const float*)d_in[19];
    const float* wfc  = (const float*)d_in[20];
    const float* bfc  = (const float*)d_in[21];
    float* out = (float*)d_out;

    static cudaStream_t s1 = nullptr, s2 = nullptr;
    static cudaEvent_t ev0, ev1, ev2;
    static void *p_degs, *p_deg, *p_gsum, *p_gcnt, *p_mom;
    if (!s1) {
        cudaStreamCreateWithFlags(&s1, cudaStreamNonBlocking);
        cudaStreamCreateWithFlags(&s2, cudaStreamNonBlocking);
        cudaEventCreateWithFlags(&ev0, cudaEventDisableTiming);
        cudaEventCreateWithFlags(&ev1, cudaEventDisableTiming);
        cudaEventCreateWithFlags(&ev2, cudaEventDisableTiming);
        cudaGetSymbolAddress(&p_degs, d_degs);
        cudaGetSymbolAddress(&p_deg,  d_deg);
        cudaGetSymbolAddress(&p_gsum, d_gsum);
        cudaGetSymbolAddress(&p_gcnt, d_gcnt);
        cudaGetSymbolAddress(&p_mom,  d_mom);
    }

    // fork
    cudaEventRecord(ev0, 0);
    cudaStreamWaitEvent(s1, ev0, 0);
    cudaStreamWaitEvent(s2, ev0, 0);

    // default: CSR prologue (critical path to k_msg)
    cudaMemsetAsync(p_degs, 0, NN * sizeof(int), 0);
    k_deg_src<<<(EE / 4 + 255) / 256, 256>>>(ei);
    k_scan<<<1, 1024>>>();
    k_scatter<<<(EE / 4 + 255) / 256, 256>>>(ei, ea);

    // s1: moments -> BN fold
    cudaMemsetAsync(p_mom, 0, 9 * sizeof(double), s1);
    k_mom<<<(EE / 4 + 255) / 256, 256, 0, s1>>>(ea);
    k_bn_both<<<1, 64, 0, s1>>>(g_0, be_0, g_1, be_1, w1_0, b1_0, w1_1, b1_1);
    cudaEventRecord(ev1, s1);

    // s2: dst degree + pool counts + layer-0 y precompute
    cudaMemsetAsync(p_deg,  0, NN * sizeof(float), s2);
    cudaMemsetAsync(p_gsum, 0, GG * DOUT * sizeof(float), s2);
    cudaMemsetAsync(p_gcnt, 0, GG * sizeof(float), s2);
    k_deg_dst<<<(EE / 4 + 255) / 256, 256, 0, s2>>>(ei, batch);
    k_y<16><<<dim3(NX, HID + 1), 128, 0, s2>>>(x, 1, w2_0, b2_0);
    cudaEventRecord(ev2, s2);

    // join
    cudaStreamWaitEvent(0, ev1, 0);
    cudaStreamWaitEvent(0, ev2, 0);

    // layer 0
    k_msg<<<(NN * 32 + 255) / 256, 256>>>(0);
    k_x<16><<<(NN * DOUT + 255) / 256, 256>>>(x, 1, wr_0, bc_0, batch, 0);

    // layer 1
    k_y<32><<<dim3(NX, HID + 1), 128>>>(nullptr, 0, w2_1, b2_1);
    k_msg<<<(NN * 32 + 255) / 256, 256>>>(1);
    k_x<32><<<(NN * DOUT + 255) / 256, 256>>>(nullptr, 0, wr_1, bc_1, batch, 1);

    // fc
    kp_out<<<1, 128>>>(wfc, bfc, out);
}